// round 12
// baseline (speedup 1.0000x reference)
#include <cuda_runtime.h>
#include <stdint.h>

#define COLS 16384
#define NTHREADS 512
#define NWARPS (NTHREADS / 32)
#define VEC (COLS / 4 / NTHREADS)   // 8 float4 (32 elems) per thread
#define BATCH 4
#define NBINS 1024
#define CAP 2048                    // candidate capacity (expected ~512)
#define MCAP 64                     // boundary-bucket member cap (fast path)

#define PIVF 1.8627f                // ~1/32 quantile of N(0,1): E[cands]=512
#define BSCALE 409.6f               // 1024 buckets over [1.8627, ~4.36]

// Monotonic float->uint key transform (order-preserving)
__device__ __forceinline__ uint32_t f2k(float f) {
    uint32_t u = __float_as_uint(f);
    return u ^ ((uint32_t)((int32_t)u >> 31) | 0x80000000u);
}
__device__ __forceinline__ float k2f(uint32_t k) {
    uint32_t mask = (~((uint32_t)((int32_t)k >> 31))) | 0x80000000u;
    return __uint_as_float(k ^ mask);
}
// Monotone bucket map for candidates (all > PIVF)
__device__ __forceinline__ int bucketf(float xv) {
    int b = (int)((xv - PIVF) * BSCALE);
    return b > (NBINS - 1) ? (NBINS - 1) : (b < 0 ? 0 : b);
}

// Find highest bin b: count(bins > b) < kneed <= count(bins >= b).
// ctrl[0]=b, ctrl[1]=count strictly above b, ctrl[2]=hist[b]. Ends with barrier.
__device__ void select_bin(const int* hist, int* warpbuf, int* ctrl, int kneed) {
    const int CH = NBINS / NTHREADS;   // 2
    int t = threadIdx.x, lane = t & 31, w = t >> 5;
    int h[CH];
    int cs = 0;
#pragma unroll
    for (int j = 0; j < CH; j++) { h[j] = hist[t * CH + j]; cs += h[j]; }
    int s = cs;
#pragma unroll
    for (int off = 1; off < 32; off <<= 1) {
        int v = __shfl_down_sync(0xffffffffu, s, off);
        if (lane + off < 32) s += v;
    }
    if (lane == 0) warpbuf[w] = s;
    __syncthreads();
    if (w == 0) {
        int wt = (lane < NWARPS) ? warpbuf[lane] : 0;
        int ws = wt;
#pragma unroll
        for (int off = 1; off < 32; off <<= 1) {
            int v = __shfl_down_sync(0xffffffffu, ws, off);
            if (lane + off < 32) ws += v;
        }
        if (lane < NWARPS) warpbuf[lane] = ws;
    }
    __syncthreads();
    int above = (w < NWARPS - 1) ? warpbuf[w + 1] : 0;
    int S_incl = s + above;
    int S_next = S_incl - cs;
    if (S_incl >= kneed && S_next < kneed) {
        int c = S_next;
#pragma unroll
        for (int j = CH - 1; j >= 0; j--) {
            if (c + h[j] >= kneed) { ctrl[0] = t * CH + j; ctrl[1] = c; ctrl[2] = h[j]; break; }
            c += h[j];
        }
    }
    __syncthreads();
}

__global__ void __launch_bounds__(NTHREADS, 3)
topk_scatter_kernel(const float* __restrict__ x, const int* __restrict__ kp,
                    float* __restrict__ out) {
    __shared__ uint32_t ckey[CAP];      // 8 KB
    __shared__ int      cidx[CAP];      // 8 KB
    __shared__ int      hist[NBINS];    // 4 KB
    __shared__ uint32_t mlist[MCAP];
    __shared__ int      warpbuf[NWARPS];
    __shared__ int      sctrl[8];
    __shared__ unsigned mmx[2];

    const int t    = threadIdx.x;
    const int lane = t & 31;
    const int w    = t >> 5;
    const int row  = blockIdx.x;
    const float4* xr = (const float4*)(x + (size_t)row * COLS);
    const float*  xrow = x + (size_t)row * COLS;
    float* outrow = out + (size_t)row * COLS;
    const int K = *kp;
    const float4 z4 = make_float4(0.f, 0.f, 0.f, 0.f);
    const bool zero_first = (row & 1);   // phase stagger: mix read/write streams per SM

    // init hist (folded bucket histogram target) + counter
    for (int i = t; i < NBINS; i += NTHREADS) hist[i] = 0;
    if (t == 0) sctrl[4] = 0;
    __syncthreads();

    // ---- odd rows: zero-fill first (write burst while even rows read) ----
    if (zero_first) {
#pragma unroll
        for (int i = 0; i < VEC; i++)
            __stcs((float4*)outrow + i * NTHREADS + t, z4);
    }

    // ============ Phase A: one read sweep, max4 early-out + push + bucket-hist ==
#pragma unroll
    for (int ii = 0; ii < VEC; ii += BATCH) {
        float4 v[BATCH];
#pragma unroll
        for (int j = 0; j < BATCH; j++) v[j] = __ldcs(&xr[(ii + j) * NTHREADS + t]);
#pragma unroll
        for (int j = 0; j < BATCH; j++) {
            // vector early-out: one compare per float4 (true ~12% of the time)
            float m4 = fmaxf(fmaxf(v[j].x, v[j].y), fmaxf(v[j].z, v[j].w));
            if (m4 > PIVF) {
                int base = 4 * ((ii + j) * NTHREADS + t);
                if (v[j].x > PIVF) { int p = atomicAdd(&sctrl[4], 1); if (p < CAP) { ckey[p] = f2k(v[j].x); cidx[p] = base + 0; atomicAdd(&hist[bucketf(v[j].x)], 1); } }
                if (v[j].y > PIVF) { int p = atomicAdd(&sctrl[4], 1); if (p < CAP) { ckey[p] = f2k(v[j].y); cidx[p] = base + 1; atomicAdd(&hist[bucketf(v[j].y)], 1); } }
                if (v[j].z > PIVF) { int p = atomicAdd(&sctrl[4], 1); if (p < CAP) { ckey[p] = f2k(v[j].z); cidx[p] = base + 2; atomicAdd(&hist[bucketf(v[j].z)], 1); } }
                if (v[j].w > PIVF) { int p = atomicAdd(&sctrl[4], 1); if (p < CAP) { ckey[p] = f2k(v[j].w); cidx[p] = base + 3; atomicAdd(&hist[bucketf(v[j].w)], 1); } }
            }
        }
    }

    // ---- even rows: zero-fill after scan (stores drain during selection) ----
    if (!zero_first) {
#pragma unroll
        for (int i = 0; i < VEC; i++)
            __stcs((float4*)outrow + i * NTHREADS + t, z4);
    }
    __syncthreads();
    int cnt = sctrl[4];

    uint32_t T = 0;
    int idx_cut = COLS;
    int needed_eq = 0, cnt_eq = 0;
    bool need_radix = false;
    bool degen = false;

    if (cnt >= K && cnt <= CAP) {
        // ======== fast select: hist already built during the scan ========
        select_bin(hist, warpbuf, sctrl, K);
        const int b = sctrl[0];
        const int kneed = K - sctrl[1];
        const int m_in_b = sctrl[2];
        __syncthreads();
        if (m_in_b <= MCAP) {
            if (t == 0) sctrl[5] = 0;
            __syncthreads();
            for (int e = t; e < cnt; e += NTHREADS) {
                uint32_t kv = ckey[e];
                if (bucketf(k2f(kv)) == b) {
                    int p = atomicAdd(&sctrl[5], 1);
                    mlist[p] = kv;
                }
            }
            __syncthreads();
            const int m = sctrl[5];
            if (t < m) {
                uint32_t mykey = mlist[t];
                int gt = 0, eq = 0;
                for (int q = 0; q < m; q++) {
                    uint32_t kq = mlist[q];
                    gt += (kq > mykey); eq += (kq == mykey);
                }
                if (gt < kneed && gt + eq >= kneed) {
                    sctrl[0] = (int)mykey; sctrl[1] = kneed - gt; sctrl[2] = eq;
                }
            }
            __syncthreads();
            T = (uint32_t)sctrl[0];
            needed_eq = sctrl[1];
            cnt_eq = sctrl[2];
        } else {
            need_radix = true;           // pathological bucket overload
        }
    } else {
        // ======== exact binary-search fallback over pivot (rare) ========
        uint32_t lo = 0u, hi = 0xFFFFFFFFu;
        uint32_t pivot = f2k(PIVF);
        if (cnt < K) hi = pivot; else lo = pivot;
        for (int iter = 0; iter < 40; iter++) {
            if (!degen) {
                if (hi - lo <= 1u) { degen = true; pivot = hi; }
                else pivot = lo + ((hi - lo) >> 1);
            }
            __syncthreads();
            if (t == 0) sctrl[4] = 0;
            __syncthreads();
#pragma unroll 2
            for (int i = 0; i < VEC; i++) {
                float4 v = xr[i * NTHREADS + t];
                int base = 4 * (i * NTHREADS + t);
                uint32_t kx = f2k(v.x), ky = f2k(v.y), kz = f2k(v.z), kw = f2k(v.w);
                if (kx > pivot) { int p = atomicAdd(&sctrl[4], 1); if (p < CAP) { ckey[p] = kx; cidx[p] = base + 0; } }
                if (ky > pivot) { int p = atomicAdd(&sctrl[4], 1); if (p < CAP) { ckey[p] = ky; cidx[p] = base + 1; } }
                if (kz > pivot) { int p = atomicAdd(&sctrl[4], 1); if (p < CAP) { ckey[p] = kz; cidx[p] = base + 2; } }
                if (kw > pivot) { int p = atomicAdd(&sctrl[4], 1); if (p < CAP) { ckey[p] = kw; cidx[p] = base + 3; } }
            }
            __syncthreads();
            cnt = sctrl[4];
            if (degen) break;
            if (cnt >= K && cnt <= CAP) break;
            if (cnt < K) hi = pivot; else lo = pivot;
        }
        if (degen) {
            // T = pivot; list holds all keys > T (cnt < K). Append first ne ties.
            T = pivot;
            const int ne = K - cnt;
            if (t == 0) sctrl[6] = 0;
            __syncthreads();
            for (int seg = 0; seg < COLS / NTHREADS; seg++) {
                int idx = seg * NTHREADS + t;
                bool tie = (f2k(xrow[idx]) == T);
                unsigned m = __ballot_sync(0xffffffffu, tie);
                int wrank = __popc(m & ((1u << lane) - 1));
                if (lane == 0) warpbuf[w] = __popc(m);
                __syncthreads();
                int base = 0;
                for (int j = 0; j < w; j++) base += warpbuf[j];
                int grank = sctrl[6] + base + wrank;
                if (tie && grank < ne) { ckey[cnt + grank] = T; cidx[cnt + grank] = idx; }
                __syncthreads();
                if (t == 0) {
                    int s = 0;
                    for (int j = 0; j < NWARPS; j++) s += warpbuf[j];
                    sctrl[6] += s;
                }
                __syncthreads();
            }
            cnt += ne;
            idx_cut = COLS;
        } else {
            need_radix = true;
        }
    }

    if (need_radix) {
        // ---- exact radix select over cnt in [K, CAP] candidates ----
        if (t == 0) { mmx[0] = 0xFFFFFFFFu; mmx[1] = 0u; }
        __syncthreads();
        {
            uint32_t mn = 0xFFFFFFFFu, mx = 0u;
            for (int e = t; e < cnt; e += NTHREADS) {
                uint32_t kv = ckey[e];
                mn = min(mn, kv); mx = max(mx, kv);
            }
#pragma unroll
            for (int off = 16; off >= 1; off >>= 1) {
                mn = min(mn, __shfl_down_sync(0xffffffffu, mn, off));
                mx = max(mx, __shfl_down_sync(0xffffffffu, mx, off));
            }
            if (lane == 0) { atomicMin(&mmx[0], mn); atomicMax(&mmx[1], mx); }
        }
        __syncthreads();
        const uint32_t mn = mmx[0], mx = mmx[1];
        if (mn == mx) {
            T = mn; needed_eq = K; cnt_eq = cnt;
        } else {
            int prefix = __clz(mn ^ mx);
            int shift_rem = 32 - prefix;
            uint32_t cur = (prefix == 0) ? 0u : (mn >> shift_rem);
            int kneed = K;
            cnt_eq = 0;
            while (shift_rem > 0) {
                int take = shift_rem > 10 ? 10 : shift_rem;
                shift_rem -= take;
                for (int i = t; i < NBINS; i += NTHREADS) hist[i] = 0;
                __syncthreads();
                uint32_t mask = (1u << take) - 1u;
                for (int e = t; e < cnt; e += NTHREADS) {
                    uint32_t kv = ckey[e];
                    if ((uint32_t)(((uint64_t)kv) >> (shift_rem + take)) == cur)
                        atomicAdd(&hist[(kv >> shift_rem) & mask], 1);
                }
                __syncthreads();
                select_bin(hist, warpbuf, sctrl, kneed);
                cur = (cur << take) | (uint32_t)sctrl[0];
                kneed -= sctrl[1];
                cnt_eq = sctrl[2];
            }
            T = cur;
            needed_eq = kneed;
        }
    }

    // ---- tie-break (rare): keep needed_eq lowest column indices among key==T ----
    if (!degen && needed_eq < cnt_eq) {
        for (int e = t; e < cnt; e += NTHREADS) {
            if (ckey[e] == T) {
                int v = cidx[e], r = 0;
                for (int q = 0; q < cnt; q++) r += (ckey[q] == T && cidx[q] < v);
                if (r == needed_eq - 1) sctrl[3] = v;
            }
        }
        __syncthreads();
        idx_cut = sctrl[3];
    }

    // ================= Phase D: scatter winners over the zero background ========
    for (int e = t; e < cnt; e += NTHREADS) {
        uint32_t kv = ckey[e];
        if (kv > T || (kv == T && cidx[e] <= idx_cut))
            outrow[cidx[e]] = k2f(kv);
    }
}

extern "C" void kernel_launch(void* const* d_in, const int* in_sizes, int n_in,
                              void* d_out, int out_size) {
    const float* x  = (const float*)d_in[0];
    const int*   kp = (const int*)d_in[1];
    float*       out = (float*)d_out;

    const int rows = in_sizes[0] / COLS;
    topk_scatter_kernel<<<rows, NTHREADS>>>(x, kp, out);
}

// round 14
// speedup vs baseline: 1.0064x; 1.0064x over previous
#include <cuda_runtime.h>
#include <stdint.h>

#define COLS 16384
#define NTHREADS 256
#define NWARPS (NTHREADS / 32)
#define VEC (COLS / 4 / NTHREADS)   // 16 float4 (64 elems) per thread
#define BATCH 4
#define NBINS 1024
#define CAP 2048                    // candidate capacity (expected ~512)
#define MCAP 64                     // boundary-bucket member cap (fast path)

#define PIVF 1.8627f                // ~1/32 quantile of N(0,1): E[cands]=512
#define BSCALE 409.6f               // 1024 buckets over [1.8627, ~4.36]

// Monotonic float->uint key transform (order-preserving)
__device__ __forceinline__ uint32_t f2k(float f) {
    uint32_t u = __float_as_uint(f);
    return u ^ ((uint32_t)((int32_t)u >> 31) | 0x80000000u);
}
__device__ __forceinline__ float k2f(uint32_t k) {
    uint32_t mask = (~((uint32_t)((int32_t)k >> 31))) | 0x80000000u;
    return __uint_as_float(k ^ mask);
}
// Monotone bucket map for candidates (all > PIVF)
__device__ __forceinline__ int bucketf(float xv) {
    int b = (int)((xv - PIVF) * BSCALE);
    return b > (NBINS - 1) ? (NBINS - 1) : (b < 0 ? 0 : b);
}

// Find highest bin b: count(bins > b) < kneed <= count(bins >= b).
// ctrl[0]=b, ctrl[1]=count strictly above b, ctrl[2]=hist[b]. Ends with barrier.
__device__ void select_bin(const int* hist, int* warpbuf, int* ctrl, int kneed) {
    const int CH = NBINS / NTHREADS;   // 4
    int t = threadIdx.x, lane = t & 31, w = t >> 5;
    int h[CH];
    int cs = 0;
#pragma unroll
    for (int j = 0; j < CH; j++) { h[j] = hist[t * CH + j]; cs += h[j]; }
    int s = cs;
#pragma unroll
    for (int off = 1; off < 32; off <<= 1) {
        int v = __shfl_down_sync(0xffffffffu, s, off);
        if (lane + off < 32) s += v;
    }
    if (lane == 0) warpbuf[w] = s;
    __syncthreads();
    if (w == 0) {
        int wt = (lane < NWARPS) ? warpbuf[lane] : 0;
        int ws = wt;
#pragma unroll
        for (int off = 1; off < 32; off <<= 1) {
            int v = __shfl_down_sync(0xffffffffu, ws, off);
            if (lane + off < 32) ws += v;
        }
        if (lane < NWARPS) warpbuf[lane] = ws;
    }
    __syncthreads();
    int above = (w < NWARPS - 1) ? warpbuf[w + 1] : 0;
    int S_incl = s + above;
    int S_next = S_incl - cs;
    if (S_incl >= kneed && S_next < kneed) {
        int c = S_next;
#pragma unroll
        for (int j = CH - 1; j >= 0; j--) {
            if (c + h[j] >= kneed) { ctrl[0] = t * CH + j; ctrl[1] = c; ctrl[2] = h[j]; break; }
            c += h[j];
        }
    }
    __syncthreads();
}

__global__ void __launch_bounds__(NTHREADS, 6)
topk_scatter_kernel(const float* __restrict__ x, const int* __restrict__ kp,
                    float* __restrict__ out) {
    __shared__ uint32_t ckey[CAP];      // 8 KB
    __shared__ int      cidx[CAP];      // 8 KB
    __shared__ int      hist[NBINS];    // 4 KB
    __shared__ uint32_t mlist[MCAP];
    __shared__ int      warpbuf[NWARPS];
    __shared__ int      sctrl[8];
    __shared__ unsigned mmx[2];

    const int t    = threadIdx.x;
    const int lane = t & 31;
    const int w    = t >> 5;
    const int row  = blockIdx.x;
    const float4* xr = (const float4*)(x + (size_t)row * COLS);
    const float*  xrow = x + (size_t)row * COLS;
    float* outrow = out + (size_t)row * COLS;
    const int K = *kp;
    const float4 z4 = make_float4(0.f, 0.f, 0.f, 0.f);
    const bool zero_first = (row & 1);   // phase stagger: mix read/write streams per SM

    // init hist (folded bucket histogram target) + counter
    for (int i = t; i < NBINS; i += NTHREADS) hist[i] = 0;
    if (t == 0) sctrl[4] = 0;
    __syncthreads();

    // ---- odd rows: zero-fill first (write burst while even rows read) ----
    if (zero_first) {
#pragma unroll
        for (int i = 0; i < VEC; i++)
            __stcs((float4*)outrow + i * NTHREADS + t, z4);
    }

    // ============ Phase A (fast): one read sweep, push + bucket-hist ============
#pragma unroll
    for (int ii = 0; ii < VEC; ii += BATCH) {
        float4 v[BATCH];
#pragma unroll
        for (int j = 0; j < BATCH; j++) v[j] = __ldcs(&xr[(ii + j) * NTHREADS + t]);
#pragma unroll
        for (int j = 0; j < BATCH; j++) {
            int base = 4 * ((ii + j) * NTHREADS + t);
            if (v[j].x > PIVF) { int p = atomicAdd(&sctrl[4], 1); if (p < CAP) { ckey[p] = f2k(v[j].x); cidx[p] = base + 0; atomicAdd(&hist[bucketf(v[j].x)], 1); } }
            if (v[j].y > PIVF) { int p = atomicAdd(&sctrl[4], 1); if (p < CAP) { ckey[p] = f2k(v[j].y); cidx[p] = base + 1; atomicAdd(&hist[bucketf(v[j].y)], 1); } }
            if (v[j].z > PIVF) { int p = atomicAdd(&sctrl[4], 1); if (p < CAP) { ckey[p] = f2k(v[j].z); cidx[p] = base + 2; atomicAdd(&hist[bucketf(v[j].z)], 1); } }
            if (v[j].w > PIVF) { int p = atomicAdd(&sctrl[4], 1); if (p < CAP) { ckey[p] = f2k(v[j].w); cidx[p] = base + 3; atomicAdd(&hist[bucketf(v[j].w)], 1); } }
        }
    }

    // ---- even rows: zero-fill after scan (stores drain during selection) ----
    if (!zero_first) {
#pragma unroll
        for (int i = 0; i < VEC; i++)
            __stcs((float4*)outrow + i * NTHREADS + t, z4);
    }
    __syncthreads();
    int cnt = sctrl[4];

    uint32_t T = 0;
    int idx_cut = COLS;
    int needed_eq = 0, cnt_eq = 0;
    bool need_radix = false;
    bool degen = false;

    if (cnt >= K && cnt <= CAP) {
        // ======== fast select: hist already built during the scan ========
        select_bin(hist, warpbuf, sctrl, K);
        const int b = sctrl[0];
        const int kneed = K - sctrl[1];
        const int m_in_b = sctrl[2];
        __syncthreads();
        if (m_in_b <= MCAP) {
            if (t == 0) sctrl[5] = 0;
            __syncthreads();
            for (int e = t; e < cnt; e += NTHREADS) {
                uint32_t kv = ckey[e];
                if (bucketf(k2f(kv)) == b) {
                    int p = atomicAdd(&sctrl[5], 1);
                    mlist[p] = kv;
                }
            }
            __syncthreads();
            const int m = sctrl[5];
            if (t < m) {
                uint32_t mykey = mlist[t];
                int gt = 0, eq = 0;
                for (int q = 0; q < m; q++) {
                    uint32_t kq = mlist[q];
                    gt += (kq > mykey); eq += (kq == mykey);
                }
                if (gt < kneed && gt + eq >= kneed) {
                    sctrl[0] = (int)mykey; sctrl[1] = kneed - gt; sctrl[2] = eq;
                }
            }
            __syncthreads();
            T = (uint32_t)sctrl[0];
            needed_eq = sctrl[1];
            cnt_eq = sctrl[2];
        } else {
            need_radix = true;           // pathological bucket overload
        }
    } else {
        // ======== exact binary-search fallback over pivot (rare) ========
        uint32_t lo = 0u, hi = 0xFFFFFFFFu;
        uint32_t pivot = f2k(PIVF);
        if (cnt < K) hi = pivot; else lo = pivot;
        for (int iter = 0; iter < 40; iter++) {
            if (!degen) {
                if (hi - lo <= 1u) { degen = true; pivot = hi; }
                else pivot = lo + ((hi - lo) >> 1);
            }
            __syncthreads();
            if (t == 0) sctrl[4] = 0;
            __syncthreads();
#pragma unroll 2
            for (int i = 0; i < VEC; i++) {
                float4 v = xr[i * NTHREADS + t];
                int base = 4 * (i * NTHREADS + t);
                uint32_t kx = f2k(v.x), ky = f2k(v.y), kz = f2k(v.z), kw = f2k(v.w);
                if (kx > pivot) { int p = atomicAdd(&sctrl[4], 1); if (p < CAP) { ckey[p] = kx; cidx[p] = base + 0; } }
                if (ky > pivot) { int p = atomicAdd(&sctrl[4], 1); if (p < CAP) { ckey[p] = ky; cidx[p] = base + 1; } }
                if (kz > pivot) { int p = atomicAdd(&sctrl[4], 1); if (p < CAP) { ckey[p] = kz; cidx[p] = base + 2; } }
                if (kw > pivot) { int p = atomicAdd(&sctrl[4], 1); if (p < CAP) { ckey[p] = kw; cidx[p] = base + 3; } }
            }
            __syncthreads();
            cnt = sctrl[4];
            if (degen) break;
            if (cnt >= K && cnt <= CAP) break;
            if (cnt < K) hi = pivot; else lo = pivot;
        }
        if (degen) {
            // T = pivot; list holds all keys > T (cnt < K). Append first ne ties.
            T = pivot;
            const int ne = K - cnt;
            if (t == 0) sctrl[6] = 0;
            __syncthreads();
            for (int seg = 0; seg < COLS / NTHREADS; seg++) {
                int idx = seg * NTHREADS + t;
                bool tie = (f2k(xrow[idx]) == T);
                unsigned m = __ballot_sync(0xffffffffu, tie);
                int wrank = __popc(m & ((1u << lane) - 1));
                if (lane == 0) warpbuf[w] = __popc(m);
                __syncthreads();
                int base = 0;
                for (int j = 0; j < w; j++) base += warpbuf[j];
                int grank = sctrl[6] + base + wrank;
                if (tie && grank < ne) { ckey[cnt + grank] = T; cidx[cnt + grank] = idx; }
                __syncthreads();
                if (t == 0) {
                    int s = 0;
                    for (int j = 0; j < NWARPS; j++) s += warpbuf[j];
                    sctrl[6] += s;
                }
                __syncthreads();
            }
            cnt += ne;
            idx_cut = COLS;
        } else {
            need_radix = true;
        }
    }

    if (need_radix) {
        // ---- exact radix select over cnt in [K, CAP] candidates ----
        if (t == 0) { mmx[0] = 0xFFFFFFFFu; mmx[1] = 0u; }
        __syncthreads();
        {
            uint32_t mn = 0xFFFFFFFFu, mx = 0u;
            for (int e = t; e < cnt; e += NTHREADS) {
                uint32_t kv = ckey[e];
                mn = min(mn, kv); mx = max(mx, kv);
            }
#pragma unroll
            for (int off = 16; off >= 1; off >>= 1) {
                mn = min(mn, __shfl_down_sync(0xffffffffu, mn, off));
                mx = max(mx, __shfl_down_sync(0xffffffffu, mx, off));
            }
            if (lane == 0) { atomicMin(&mmx[0], mn); atomicMax(&mmx[1], mx); }
        }
        __syncthreads();
        const uint32_t mn = mmx[0], mx = mmx[1];
        if (mn == mx) {
            T = mn; needed_eq = K; cnt_eq = cnt;
        } else {
            int prefix = __clz(mn ^ mx);
            int shift_rem = 32 - prefix;
            uint32_t cur = (prefix == 0) ? 0u : (mn >> shift_rem);
            int kneed = K;
            cnt_eq = 0;
            while (shift_rem > 0) {
                int take = shift_rem > 10 ? 10 : shift_rem;
                shift_rem -= take;
                for (int i = t; i < NBINS; i += NTHREADS) hist[i] = 0;
                __syncthreads();
                uint32_t mask = (1u << take) - 1u;
                for (int e = t; e < cnt; e += NTHREADS) {
                    uint32_t kv = ckey[e];
                    if ((uint32_t)(((uint64_t)kv) >> (shift_rem + take)) == cur)
                        atomicAdd(&hist[(kv >> shift_rem) & mask], 1);
                }
                __syncthreads();
                select_bin(hist, warpbuf, sctrl, kneed);
                cur = (cur << take) | (uint32_t)sctrl[0];
                kneed -= sctrl[1];
                cnt_eq = sctrl[2];
            }
            T = cur;
            needed_eq = kneed;
        }
    }

    // ---- tie-break (rare): keep needed_eq lowest column indices among key==T ----
    if (!degen && needed_eq < cnt_eq) {
        for (int e = t; e < cnt; e += NTHREADS) {
            if (ckey[e] == T) {
                int v = cidx[e], r = 0;
                for (int q = 0; q < cnt; q++) r += (ckey[q] == T && cidx[q] < v);
                if (r == needed_eq - 1) sctrl[3] = v;
            }
        }
        __syncthreads();
        idx_cut = sctrl[3];
    }

    // ================= Phase D: scatter winners over the zero background ========
    for (int e = t; e < cnt; e += NTHREADS) {
        uint32_t kv = ckey[e];
        if (kv > T || (kv == T && cidx[e] <= idx_cut))
            outrow[cidx[e]] = k2f(kv);
    }
}

extern "C" void kernel_launch(void* const* d_in, const int* in_sizes, int n_in,
                              void* d_out, int out_size) {
    const float* x  = (const float*)d_in[0];
    const int*   kp = (const int*)d_in[1];
    float*       out = (float*)d_out;

    const int rows = in_sizes[0] / COLS;
    topk_scatter_kernel<<<rows, NTHREADS>>>(x, kp, out);
}

// round 16
// speedup vs baseline: 1.0698x; 1.0630x over previous
#include <cuda_runtime.h>
#include <stdint.h>

#define COLS 16384
#define NTHREADS 512
#define NWARPS (NTHREADS / 32)
#define VEC (COLS / 4 / NTHREADS)   // 8 float4 (32 elems) per thread
#define BATCH 4
#define NBINS 1024
#define CAP 2048                    // candidate capacity (expected ~512)
#define MCAP 64                     // boundary-bucket member cap (fast path)

#define PIVF 1.8627f                // ~1/32 quantile of N(0,1): E[cands]=512
#define BSCALE 409.6f               // 1024 buckets over [1.8627, ~4.36]

// Monotonic float->uint key transform (order-preserving)
__device__ __forceinline__ uint32_t f2k(float f) {
    uint32_t u = __float_as_uint(f);
    return u ^ ((uint32_t)((int32_t)u >> 31) | 0x80000000u);
}
__device__ __forceinline__ float k2f(uint32_t k) {
    uint32_t mask = (~((uint32_t)((int32_t)k >> 31))) | 0x80000000u;
    return __uint_as_float(k ^ mask);
}
// Monotone bucket map for candidates (all > PIVF)
__device__ __forceinline__ int bucketf(float xv) {
    int b = (int)((xv - PIVF) * BSCALE);
    return b > (NBINS - 1) ? (NBINS - 1) : (b < 0 ? 0 : b);
}

// Find highest bin b: count(bins > b) < kneed <= count(bins >= b).
// ctrl[0]=b, ctrl[1]=count strictly above b, ctrl[2]=hist[b]. Ends with barrier.
__device__ void select_bin(const int* hist, int* warpbuf, int* ctrl, int kneed) {
    const int CH = NBINS / NTHREADS;   // 2
    int t = threadIdx.x, lane = t & 31, w = t >> 5;
    int h[CH];
    int cs = 0;
#pragma unroll
    for (int j = 0; j < CH; j++) { h[j] = hist[t * CH + j]; cs += h[j]; }
    int s = cs;
#pragma unroll
    for (int off = 1; off < 32; off <<= 1) {
        int v = __shfl_down_sync(0xffffffffu, s, off);
        if (lane + off < 32) s += v;
    }
    if (lane == 0) warpbuf[w] = s;
    __syncthreads();
    if (w == 0) {
        int wt = (lane < NWARPS) ? warpbuf[lane] : 0;
        int ws = wt;
#pragma unroll
        for (int off = 1; off < 32; off <<= 1) {
            int v = __shfl_down_sync(0xffffffffu, ws, off);
            if (lane + off < 32) ws += v;
        }
        if (lane < NWARPS) warpbuf[lane] = ws;
    }
    __syncthreads();
    int above = (w < NWARPS - 1) ? warpbuf[w + 1] : 0;
    int S_incl = s + above;
    int S_next = S_incl - cs;
    if (S_incl >= kneed && S_next < kneed) {
        int c = S_next;
#pragma unroll
        for (int j = CH - 1; j >= 0; j--) {
            if (c + h[j] >= kneed) { ctrl[0] = t * CH + j; ctrl[1] = c; ctrl[2] = h[j]; break; }
            c += h[j];
        }
    }
    __syncthreads();
}

__global__ void __launch_bounds__(NTHREADS, 3)
topk_scatter_kernel(const float* __restrict__ x, const int* __restrict__ kp,
                    float* __restrict__ out) {
    __shared__ uint32_t ckey[CAP];      // 8 KB
    __shared__ int      cidx[CAP];      // 8 KB
    __shared__ int      hist[NBINS];    // 4 KB
    __shared__ uint32_t mlist[MCAP];
    __shared__ int      warpbuf[NWARPS];
    __shared__ int      sctrl[8];
    __shared__ unsigned mmx[2];

    const int t    = threadIdx.x;
    const int lane = t & 31;
    const int w    = t >> 5;
    const int row  = blockIdx.x;
    const float4* xr = (const float4*)(x + (size_t)row * COLS);
    const float*  xrow = x + (size_t)row * COLS;
    float* outrow = out + (size_t)row * COLS;
    const int K = *kp;
    const float4 z4 = make_float4(0.f, 0.f, 0.f, 0.f);
    // Phase stagger that survives SM placement: co-resident CTAs on one SM have
    // bids spaced ~148 (even), so (row & 1) alone is constant per SM. Adding the
    // wave index (row/148) flips parity between same-SM neighbors.
    const bool zero_first = ((row + row / 148) & 1);

    // init hist (folded bucket histogram target) + counter
    for (int i = t; i < NBINS; i += NTHREADS) hist[i] = 0;
    if (t == 0) sctrl[4] = 0;
    __syncthreads();

    // ---- zero_first rows: write burst first (write-through: no dirty L2) ----
    if (zero_first) {
#pragma unroll
        for (int i = 0; i < VEC; i++)
            __stwt((float4*)outrow + i * NTHREADS + t, z4);
    }

    // ============ Phase A (fast): one read sweep, push + bucket-hist ============
#pragma unroll
    for (int ii = 0; ii < VEC; ii += BATCH) {
        float4 v[BATCH];
#pragma unroll
        for (int j = 0; j < BATCH; j++) v[j] = __ldcs(&xr[(ii + j) * NTHREADS + t]);
#pragma unroll
        for (int j = 0; j < BATCH; j++) {
            int base = 4 * ((ii + j) * NTHREADS + t);
            if (v[j].x > PIVF) { int p = atomicAdd(&sctrl[4], 1); if (p < CAP) { ckey[p] = f2k(v[j].x); cidx[p] = base + 0; atomicAdd(&hist[bucketf(v[j].x)], 1); } }
            if (v[j].y > PIVF) { int p = atomicAdd(&sctrl[4], 1); if (p < CAP) { ckey[p] = f2k(v[j].y); cidx[p] = base + 1; atomicAdd(&hist[bucketf(v[j].y)], 1); } }
            if (v[j].z > PIVF) { int p = atomicAdd(&sctrl[4], 1); if (p < CAP) { ckey[p] = f2k(v[j].z); cidx[p] = base + 2; atomicAdd(&hist[bucketf(v[j].z)], 1); } }
            if (v[j].w > PIVF) { int p = atomicAdd(&sctrl[4], 1); if (p < CAP) { ckey[p] = f2k(v[j].w); cidx[p] = base + 3; atomicAdd(&hist[bucketf(v[j].w)], 1); } }
        }
    }

    // ---- other rows: zero-fill after scan (stores drain during selection) ----
    if (!zero_first) {
#pragma unroll
        for (int i = 0; i < VEC; i++)
            __stwt((float4*)outrow + i * NTHREADS + t, z4);
    }
    __syncthreads();
    int cnt = sctrl[4];

    uint32_t T = 0;
    int idx_cut = COLS;
    int needed_eq = 0, cnt_eq = 0;
    bool need_radix = false;
    bool degen = false;

    if (cnt >= K && cnt <= CAP) {
        // ======== fast select: hist already built during the scan ========
        select_bin(hist, warpbuf, sctrl, K);
        const int b = sctrl[0];
        const int kneed = K - sctrl[1];
        const int m_in_b = sctrl[2];
        __syncthreads();
        if (m_in_b <= MCAP) {
            if (t == 0) sctrl[5] = 0;
            __syncthreads();
            for (int e = t; e < cnt; e += NTHREADS) {
                uint32_t kv = ckey[e];
                if (bucketf(k2f(kv)) == b) {
                    int p = atomicAdd(&sctrl[5], 1);
                    mlist[p] = kv;
                }
            }
            __syncthreads();
            const int m = sctrl[5];
            if (t < m) {
                uint32_t mykey = mlist[t];
                int gt = 0, eq = 0;
                for (int q = 0; q < m; q++) {
                    uint32_t kq = mlist[q];
                    gt += (kq > mykey); eq += (kq == mykey);
                }
                if (gt < kneed && gt + eq >= kneed) {
                    sctrl[0] = (int)mykey; sctrl[1] = kneed - gt; sctrl[2] = eq;
                }
            }
            __syncthreads();
            T = (uint32_t)sctrl[0];
            needed_eq = sctrl[1];
            cnt_eq = sctrl[2];
        } else {
            need_radix = true;           // pathological bucket overload
        }
    } else {
        // ======== exact binary-search fallback over pivot (rare) ========
        uint32_t lo = 0u, hi = 0xFFFFFFFFu;
        uint32_t pivot = f2k(PIVF);
        if (cnt < K) hi = pivot; else lo = pivot;
        for (int iter = 0; iter < 40; iter++) {
            if (!degen) {
                if (hi - lo <= 1u) { degen = true; pivot = hi; }
                else pivot = lo + ((hi - lo) >> 1);
            }
            __syncthreads();
            if (t == 0) sctrl[4] = 0;
            __syncthreads();
#pragma unroll 2
            for (int i = 0; i < VEC; i++) {
                float4 v = xr[i * NTHREADS + t];
                int base = 4 * (i * NTHREADS + t);
                uint32_t kx = f2k(v.x), ky = f2k(v.y), kz = f2k(v.z), kw = f2k(v.w);
                if (kx > pivot) { int p = atomicAdd(&sctrl[4], 1); if (p < CAP) { ckey[p] = kx; cidx[p] = base + 0; } }
                if (ky > pivot) { int p = atomicAdd(&sctrl[4], 1); if (p < CAP) { ckey[p] = ky; cidx[p] = base + 1; } }
                if (kz > pivot) { int p = atomicAdd(&sctrl[4], 1); if (p < CAP) { ckey[p] = kz; cidx[p] = base + 2; } }
                if (kw > pivot) { int p = atomicAdd(&sctrl[4], 1); if (p < CAP) { ckey[p] = kw; cidx[p] = base + 3; } }
            }
            __syncthreads();
            cnt = sctrl[4];
            if (degen) break;
            if (cnt >= K && cnt <= CAP) break;
            if (cnt < K) hi = pivot; else lo = pivot;
        }
        if (degen) {
            // T = pivot; list holds all keys > T (cnt < K). Append first ne ties.
            T = pivot;
            const int ne = K - cnt;
            if (t == 0) sctrl[6] = 0;
            __syncthreads();
            for (int seg = 0; seg < COLS / NTHREADS; seg++) {
                int idx = seg * NTHREADS + t;
                bool tie = (f2k(xrow[idx]) == T);
                unsigned m = __ballot_sync(0xffffffffu, tie);
                int wrank = __popc(m & ((1u << lane) - 1));
                if (lane == 0) warpbuf[w] = __popc(m);
                __syncthreads();
                int base = 0;
                for (int j = 0; j < w; j++) base += warpbuf[j];
                int grank = sctrl[6] + base + wrank;
                if (tie && grank < ne) { ckey[cnt + grank] = T; cidx[cnt + grank] = idx; }
                __syncthreads();
                if (t == 0) {
                    int s = 0;
                    for (int j = 0; j < NWARPS; j++) s += warpbuf[j];
                    sctrl[6] += s;
                }
                __syncthreads();
            }
            cnt += ne;
            idx_cut = COLS;
        } else {
            need_radix = true;
        }
    }

    if (need_radix) {
        // ---- exact radix select over cnt in [K, CAP] candidates ----
        if (t == 0) { mmx[0] = 0xFFFFFFFFu; mmx[1] = 0u; }
        __syncthreads();
        {
            uint32_t mn = 0xFFFFFFFFu, mx = 0u;
            for (int e = t; e < cnt; e += NTHREADS) {
                uint32_t kv = ckey[e];
                mn = min(mn, kv); mx = max(mx, kv);
            }
#pragma unroll
            for (int off = 16; off >= 1; off >>= 1) {
                mn = min(mn, __shfl_down_sync(0xffffffffu, mn, off));
                mx = max(mx, __shfl_down_sync(0xffffffffu, mx, off));
            }
            if (lane == 0) { atomicMin(&mmx[0], mn); atomicMax(&mmx[1], mx); }
        }
        __syncthreads();
        const uint32_t mn = mmx[0], mx = mmx[1];
        if (mn == mx) {
            T = mn; needed_eq = K; cnt_eq = cnt;
        } else {
            int prefix = __clz(mn ^ mx);
            int shift_rem = 32 - prefix;
            uint32_t cur = (prefix == 0) ? 0u : (mn >> shift_rem);
            int kneed = K;
            cnt_eq = 0;
            while (shift_rem > 0) {
                int take = shift_rem > 10 ? 10 : shift_rem;
                shift_rem -= take;
                for (int i = t; i < NBINS; i += NTHREADS) hist[i] = 0;
                __syncthreads();
                uint32_t mask = (1u << take) - 1u;
                for (int e = t; e < cnt; e += NTHREADS) {
                    uint32_t kv = ckey[e];
                    if ((uint32_t)(((uint64_t)kv) >> (shift_rem + take)) == cur)
                        atomicAdd(&hist[(kv >> shift_rem) & mask], 1);
                }
                __syncthreads();
                select_bin(hist, warpbuf, sctrl, kneed);
                cur = (cur << take) | (uint32_t)sctrl[0];
                kneed -= sctrl[1];
                cnt_eq = sctrl[2];
            }
            T = cur;
            needed_eq = kneed;
        }
    }

    // ---- tie-break (rare): keep needed_eq lowest column indices among key==T ----
    if (!degen && needed_eq < cnt_eq) {
        for (int e = t; e < cnt; e += NTHREADS) {
            if (ckey[e] == T) {
                int v = cidx[e], r = 0;
                for (int q = 0; q < cnt; q++) r += (ckey[q] == T && cidx[q] < v);
                if (r == needed_eq - 1) sctrl[3] = v;
            }
        }
        __syncthreads();
        idx_cut = sctrl[3];
    }

    // ================= Phase D: scatter winners over the zero background ========
    for (int e = t; e < cnt; e += NTHREADS) {
        uint32_t kv = ckey[e];
        if (kv > T || (kv == T && cidx[e] <= idx_cut))
            outrow[cidx[e]] = k2f(kv);
    }
}

extern "C" void kernel_launch(void* const* d_in, const int* in_sizes, int n_in,
                              void* d_out, int out_size) {
    const float* x  = (const float*)d_in[0];
    const int*   kp = (const int*)d_in[1];
    float*       out = (float*)d_out;

    const int rows = in_sizes[0] / COLS;
    topk_scatter_kernel<<<rows, NTHREADS>>>(x, kp, out);
}